// round 1
// baseline (speedup 1.0000x reference)
#include <cuda_runtime.h>
#include <math.h>

#define NN     2048
#define NFEAT  512
#define NHID   128
#define NHEADS 4
#define NP     3
#define PH     (NP*NHEADS)
#define ALPHA  0.2f

// ---------------- scratch (device globals: no allocation allowed) ----------------
__device__ float g_h [PH * NN * NHID];           // 12.6 MB  h[p][head][n][d]
__device__ float g_m [NP * NN * (NHEADS*NHID)];  // 12.6 MB  m[p][n][head*128+d]
__device__ float g_sv [PH * NN];
__device__ float g_Es [PH * NN];
__device__ float g_Eas[PH * NN];
__device__ float g_dv [PH * NN];
__device__ float g_Ed [PH * NN];
__device__ float g_Ead[PH * NN];
__device__ float g_scores[NP];

// ---------------- k0: zero the score accumulators ----------------
__global__ void k0_init() {
    if (threadIdx.x < NP) g_scores[threadIdx.x] = 0.f;
}

// ---------------- k1: h[ph] = x @ W_node[ph]   (2048x512x128 per ph) ----------------
__global__ __launch_bounds__(256) void k1_node_gemm(const float* __restrict__ x,
                                                    const float* __restrict__ Wn) {
    __shared__ float xs[64][33];
    __shared__ float ws[32 * 128];
    int ph   = blockIdx.y;
    int row0 = blockIdx.x * 64;
    const float* W = Wn + (size_t)ph * NFEAT * NHID;
    int tid = threadIdx.x;
    int rg = tid >> 4;   // 16 row groups  -> rows rg*4..+4
    int cg = tid & 15;   // 16 col groups  -> cols cg*8..+8

    float acc[4][8];
#pragma unroll
    for (int r = 0; r < 4; r++)
#pragma unroll
        for (int c = 0; c < 8; c++) acc[r][c] = 0.f;

    for (int k0 = 0; k0 < NFEAT; k0 += 32) {
        for (int i = tid; i < 64 * 32; i += 256)
            xs[i >> 5][i & 31] = x[(size_t)(row0 + (i >> 5)) * NFEAT + k0 + (i & 31)];
        for (int i = tid * 4; i < 32 * 128; i += 1024)
            *(float4*)&ws[i] = *(const float4*)&W[(size_t)k0 * 128 + i];
        __syncthreads();
#pragma unroll
        for (int k = 0; k < 32; k++) {
            float xv[4];
#pragma unroll
            for (int r = 0; r < 4; r++) xv[r] = xs[rg * 4 + r][k];
            float4 w0 = *(float4*)&ws[k * 128 + cg * 8];
            float4 w1 = *(float4*)&ws[k * 128 + cg * 8 + 4];
            float wv[8] = {w0.x, w0.y, w0.z, w0.w, w1.x, w1.y, w1.z, w1.w};
#pragma unroll
            for (int r = 0; r < 4; r++)
#pragma unroll
                for (int c = 0; c < 8; c++) acc[r][c] += xv[r] * wv[c];
        }
        __syncthreads();
    }
    float* hd = g_h + (size_t)ph * NN * NHID;
#pragma unroll
    for (int r = 0; r < 4; r++) {
        float* dst = hd + (size_t)(row0 + rg * 4 + r) * NHID + cg * 8;
        *(float4*)dst       = make_float4(acc[r][0], acc[r][1], acc[r][2], acc[r][3]);
        *(float4*)(dst + 4) = make_float4(acc[r][4], acc[r][5], acc[r][6], acc[r][7]);
    }
}

// ---------------- k2: s,d dots + the 4 exp vectors (factorized leakyrelu-exp) ----------------
__global__ __launch_bounds__(256) void k2_sd(const float* __restrict__ an) {
    int gw   = blockIdx.x * 8 + (threadIdx.x >> 5);   // one warp per (ph, n)
    int lane = threadIdx.x & 31;
    int ph = gw >> 11;
    int n  = gw & 2047;
    const float* hrow = g_h + ((size_t)ph * NN + n) * NHID;
    const float* a    = an + (size_t)ph * 2 * NHID;
    float s = 0.f, d = 0.f;
#pragma unroll
    for (int i = lane; i < NHID; i += 32) {
        float hv = hrow[i];
        s += hv * a[i];
        d += hv * a[NHID + i];
    }
#pragma unroll
    for (int off = 16; off; off >>= 1) {
        s += __shfl_xor_sync(0xffffffffu, s, off);
        d += __shfl_xor_sync(0xffffffffu, d, off);
    }
    if (lane == 0) {
        int idx = ph * NN + n;
        g_sv[idx] = s; g_Es[idx] = expf(s); g_Eas[idx] = expf(ALPHA * s);
        g_dv[idx] = d; g_Ed[idx] = expf(d); g_Ead[idx] = expf(ALPHA * d);
    }
}

// ---------------- k3: fused masked attention + (num @ h) + softmax-div + elu ----------------
// block: 128 threads, 64 rows x 128 dims output tile; loop m in chunks of 32.
__global__ __launch_bounds__(128) void k3_attn(const float* __restrict__ adjs) {
    __shared__ float s_sh[64], Es_sh[64], Eas_sh[64];
    __shared__ float dv_sh[32], Ed_sh[32], Ead_sh[32];
    __shared__ float adj_sh[64][33];   // padded: conflict-free column reads
    __shared__ float num[32][64];      // m-major for vectorized FMA-phase reads
    __shared__ float hs[32 * 128];
    __shared__ float rowpart[2][64];

    int ph   = blockIdx.y;
    int p    = ph >> 2, head = ph & 3;
    int row0 = blockIdx.x * 64;
    int tid  = threadIdx.x;

    if (tid < 64) {
        int idx = ph * NN + row0 + tid;
        s_sh[tid] = g_sv[idx]; Es_sh[tid] = g_Es[idx]; Eas_sh[tid] = g_Eas[idx];
    }
    int rg = tid >> 4;        // 8 row groups  -> rows rg*8..+8
    int cg = tid & 15;        // 16 col groups -> cols cg*8..+8
    int half = tid >> 6;      // num-phase: 2 threads per row
    int nn   = tid & 63;

    const float* adjbase = adjs + (size_t)p * NN * NN;
    const float* hbase   = g_h + (size_t)ph * NN * NHID;

    float acc[8][8];
#pragma unroll
    for (int r = 0; r < 8; r++)
#pragma unroll
        for (int c = 0; c < 8; c++) acc[r][c] = 0.f;
    float myrowsum = 0.f;

    for (int m0 = 0; m0 < NN; m0 += 32) {
        if (tid < 32) {
            int idx = ph * NN + m0 + tid;
            dv_sh[tid] = g_dv[idx]; Ed_sh[tid] = g_Ed[idx]; Ead_sh[tid] = g_Ead[idx];
        }
        const float* hsrc = hbase + (size_t)m0 * NHID;
#pragma unroll
        for (int i = tid * 4; i < 32 * 128; i += 512)
            *(float4*)&hs[i] = *(const float4*)&hsrc[i];
        // coalesced adj tile load (rows of 32 floats)
#pragma unroll
        for (int i = tid; i < 64 * 32; i += 128)
            adj_sh[i >> 5][i & 31] = adjbase[(size_t)(row0 + (i >> 5)) * NN + m0 + (i & 31)];
        __syncthreads();

        // ---- numerator phase: no exp, just select of precomputed products ----
        {
            float svv = s_sh[nn], Esv = Es_sh[nn], Easv = Eas_sh[nn];
            int mb = half * 16;
            float lsum = 0.f;
#pragma unroll
            for (int j = 0; j < 16; j++) {
                int mm = mb + j;
                float t = svv + dv_sh[mm];
                float w = (t > 0.f) ? (Esv * Ed_sh[mm]) : (Easv * Ead_sh[mm]);
                float v = (adj_sh[nn][mm] > 0.f) ? w : 0.f;
                num[mm][nn] = v;
                lsum += v;
            }
            myrowsum += lsum;
        }
        __syncthreads();

        // ---- FMA phase: acc += num^T-tile outer products with h tile ----
#pragma unroll
        for (int mm = 0; mm < 32; mm++) {
            float4 a0 = *(float4*)&num[mm][rg * 8];
            float4 a1 = *(float4*)&num[mm][rg * 8 + 4];
            float4 b0 = *(float4*)&hs[mm * 128 + cg * 8];
            float4 b1 = *(float4*)&hs[mm * 128 + cg * 8 + 4];
            float av[8] = {a0.x, a0.y, a0.z, a0.w, a1.x, a1.y, a1.z, a1.w};
            float bv[8] = {b0.x, b0.y, b0.z, b0.w, b1.x, b1.y, b1.z, b1.w};
#pragma unroll
            for (int r = 0; r < 8; r++)
#pragma unroll
                for (int c = 0; c < 8; c++) acc[r][c] += av[r] * bv[c];
        }
        __syncthreads();
    }

    rowpart[half][nn] = myrowsum;
    __syncthreads();

    float* mdst = g_m + ((size_t)p * NN + row0) * (NHEADS * NHID) + head * NHID;
#pragma unroll
    for (int r = 0; r < 8; r++) {
        int n = rg * 8 + r;
        float rs  = rowpart[0][n] + rowpart[1][n];
        float inv = (rs > 0.f) ? (1.f / rs) : 0.f;
        float v[8];
#pragma unroll
        for (int c = 0; c < 8; c++) {
            float t = acc[r][c] * inv;
            v[c] = (t > 0.f) ? t : expm1f(t);   // elu
        }
        float* dst = mdst + (size_t)n * (NHEADS * NHID) + cg * 8;
        *(float4*)dst       = make_float4(v[0], v[1], v[2], v[3]);
        *(float4*)(dst + 4) = make_float4(v[4], v[5], v[6], v[7]);
    }
}

// ---------------- k4: semantic attention scores (tanh(m@W+b)·q, summed per p) ----------------
__global__ __launch_bounds__(256) void k4_sem(const float* __restrict__ Wsem,
                                              const float* __restrict__ bsem,
                                              const float* __restrict__ qsem) {
    __shared__ float msh[32][65];
    __shared__ float wsh[64 * 128];
    __shared__ float red[8];
    int row0 = blockIdx.x * 32;        // rows of flat (p*n); 2048%32==0 -> single p per block
    int pidx = row0 / NN;
    int tid = threadIdx.x;
    int rg = tid >> 5;                  // 8 row groups -> rows rg*4..+4
    int cg = tid & 31;                  // 32 col groups -> cols cg*4..+4

    float acc[4][4];
#pragma unroll
    for (int r = 0; r < 4; r++)
#pragma unroll
        for (int c = 0; c < 4; c++) acc[r][c] = 0.f;

    for (int k0 = 0; k0 < 512; k0 += 64) {
        for (int i = tid; i < 32 * 64; i += 256)
            msh[i >> 6][i & 63] = g_m[(size_t)(row0 + (i >> 6)) * 512 + k0 + (i & 63)];
        for (int i = tid * 4; i < 64 * 128; i += 1024)
            *(float4*)&wsh[i] = *(const float4*)&Wsem[(size_t)k0 * 128 + i];
        __syncthreads();
#pragma unroll
        for (int k = 0; k < 64; k++) {
            float mv[4];
#pragma unroll
            for (int r = 0; r < 4; r++) mv[r] = msh[rg * 4 + r][k];
            float4 wv = *(float4*)&wsh[k * 128 + cg * 4];
            float wva[4] = {wv.x, wv.y, wv.z, wv.w};
#pragma unroll
            for (int r = 0; r < 4; r++)
#pragma unroll
                for (int c = 0; c < 4; c++) acc[r][c] += mv[r] * wva[c];
        }
        __syncthreads();
    }
    float part = 0.f;
#pragma unroll
    for (int c = 0; c < 4; c++) {
        int col = cg * 4 + c;
        float b = bsem[col], q = qsem[col];
#pragma unroll
        for (int r = 0; r < 4; r++)
            part += tanhf(acc[r][c] + b) * q;
    }
#pragma unroll
    for (int off = 16; off; off >>= 1)
        part += __shfl_xor_sync(0xffffffffu, part, off);
    if ((tid & 31) == 0) red[tid >> 5] = part;
    __syncthreads();
    if (tid == 0) {
        float tot = 0.f;
#pragma unroll
        for (int i = 0; i < 8; i++) tot += red[i];
        atomicAdd(&g_scores[pidx], tot);
    }
}

// ---------------- k6: softmax over 3 scores + weighted combine ----------------
__global__ __launch_bounds__(256) void k6_out(float* __restrict__ out) {
    __shared__ float w[NP];
    if (threadIdx.x == 0) {
        float s0 = g_scores[0] * (1.f / NN);
        float s1 = g_scores[1] * (1.f / NN);
        float s2 = g_scores[2] * (1.f / NN);
        float mx = fmaxf(s0, fmaxf(s1, s2));
        float e0 = expf(s0 - mx), e1 = expf(s1 - mx), e2 = expf(s2 - mx);
        float inv = 1.f / (e0 + e1 + e2);
        w[0] = e0 * inv; w[1] = e1 * inv; w[2] = e2 * inv;
    }
    __syncthreads();
    size_t i = (size_t)blockIdx.x * blockDim.x + threadIdx.x;
    const size_t stride = (size_t)NN * 512;
    out[i] = w[0] * g_m[i] + w[1] * g_m[stride + i] + w[2] * g_m[2 * stride + i];
}

// ---------------- launch ----------------
extern "C" void kernel_launch(void* const* d_in, const int* in_sizes, int n_in,
                              void* d_out, int out_size) {
    const float* x    = (const float*)d_in[0];
    const float* adjs = (const float*)d_in[1];
    const float* Wn   = (const float*)d_in[2];
    const float* an   = (const float*)d_in[3];
    const float* Wsem = (const float*)d_in[4];
    const float* bsem = (const float*)d_in[5];
    const float* qsem = (const float*)d_in[6];
    float* out = (float*)d_out;

    k0_init<<<1, 32>>>();
    k1_node_gemm<<<dim3(NN / 64, PH), 256>>>(x, Wn);
    k2_sd<<<(PH * NN) / 8, 256>>>(an);
    k3_attn<<<dim3(NN / 64, PH), 128>>>(adjs);
    k4_sem<<<(NP * NN) / 32, 256>>>(Wsem, bsem, qsem);
    k6_out<<<(NN * 512) / 256, 256>>>(out);
}